// round 14
// baseline (speedup 1.0000x reference)
#include <cuda_runtime.h>

#define NN 64
#define SS 60
#define BATCH 512
#define SEX 10
#define ROWS 4
#define NBG (BATCH / ROWS)
#define NACT 5
#define NROLE 7
#define OO 8
#define II 8

#define MAXSS 1024
#define ECAP 6
#define PCAP 2
#define NSLOT 12
#define NT 448

// ---- phase-1 smem layout (float offsets) ----
#define OFF_WIH  0          // [dir][180][60] = 21600
#define OFF_BHH  21600      // [dir][g*60+o] = 360
#define OFF_BIH  21960      // [dir][180]
#define OFF_BP   22320      // [dir][60]
#define OFF_HAS  22440      // [b][64] = 256
#define OFF_WU   22696      // [dir][7][60] = 840
#define OFF_HBS  23536      // [dir][slot][b][64] = 2*12*256 = 6144
#define OFF_HSB  29680      // [dir][slot][o*4+b] = 2*12*240 = 5760
#define OFF_SBUF 35440      // [dir][sbuf][4][240] = 2*6*960 = 11520
#define OFF_RHO  46960      // [dir][rbuf][240] = 960
#define OFF_ZBUF 47920      // [dir][rbuf][80] = 320
#define SMEM_FLOATS 48240
#define SMEM_BYTES (SMEM_FLOATS * 4)

// ---- global scratch ----
__device__ float g_gi_f[(size_t)NN * NBG * 3 * SS * 4];
__device__ float g_gi_b[(size_t)NN * NBG * 3 * SS * 4];
__device__ float g_alpha_f[(size_t)BATCH * SS];
__device__ float g_alpha_b[(size_t)BATCH * SS];
__device__ float g_psi_f[(size_t)BATCH * NROLE * NN];
__device__ float g_psi_b[(size_t)BATCH * NROLE * NN];

// schedule
__device__ int g_nss;
__device__ int g_eoff[2][MAXSS + 1];
__device__ int g_erec[2][900];
__device__ int g_poff[2][MAXSS + 1];
__device__ int g_prec[2][96];

__device__ __forceinline__ float sigm(float x) {
    return __fdividef(1.f, 1.f + __expf(-x));
}
__device__ __forceinline__ float tanh_f(float x) {
    float e = __expf(2.f * x);
    return 1.f - __fdividef(2.f, e + 1.f);
}
__device__ __forceinline__ void fma2(unsigned long long& d, unsigned long long a,
                                     unsigned long long b) {
    asm("fma.rn.f32x2 %0, %1, %2, %0;" : "+l"(d) : "l"(a), "l"(b));
}
__device__ __forceinline__ unsigned long long splat2(float w) {
    unsigned long long r;
    asm("mov.b64 %0, {%1, %1};" : "=l"(r) : "f"(w));
    return r;
}
__device__ __forceinline__ float lo32(unsigned long long v) {
    return __uint_as_float((unsigned)v);
}
__device__ __forceinline__ float hi32(unsigned long long v) {
    return __uint_as_float((unsigned)(v >> 32));
}

// ============================ setup: build schedule ============================
__global__ void setup_kernel(const int* adj)
{
    __shared__ unsigned long long s_pm[NN], s_sk[NN];
    __shared__ short s_ecnt[2][MAXSS], s_pcnt[2][MAXSS];
    __shared__ short s_ecur[2][MAXSS], s_pcur[2][MAXSS];
    __shared__ short s_eSS[2][900];
    __shared__ int   s_eRec[2][900];
    __shared__ short s_pSS[2][96];
    __shared__ int   s_pRec[2][96];
    __shared__ int s_nssv[2];
    const int t = threadIdx.x;

    for (int i = t; i < MAXSS; i += blockDim.x) {
        s_ecnt[0][i] = 0; s_ecnt[1][i] = 0;
        s_pcnt[0][i] = 0; s_pcnt[1][i] = 0;
        s_ecur[0][i] = 0; s_ecur[1][i] = 0;
        s_pcur[0][i] = 0; s_pcur[1][i] = 0;
    }
    if (t < NN) {
        unsigned long long pm = 0ull, sk = 0ull;
        for (int j = 0; j < NN; j++) {
            if (adj[j * NN + t]) pm |= 1ull << j;
            if (adj[t * NN + j]) sk |= 1ull << j;
        }
        s_pm[t] = pm; s_sk[t] = sk;
    }
    __syncthreads();

    if (t == 0 || t == 32) {                 // two scheduler threads, separate warps
        const int dir = (t == 32) ? 1 : 0;
        int finish[NN];
        int slotFree[NSLOT];
        for (int q = 0; q < NSLOT; q++) slotFree[q] = 0;
        int ne = 0, np = 0, maxss = 0;

        for (int k = 0; k <= NN; k++) {       // NN targets + 1 alpha target
            unsigned long long m;
            int tgt;
            bool isalpha = (k == NN);
            if (!isalpha) {
                tgt = dir ? (NN - 1 - k) : k;
                m = dir ? s_sk[tgt] : s_pm[tgt];
            } else {
                tgt = 0;
                m = 0ull;
                if (dir == 0) for (int i2 = NN - OO; i2 < NN; i2++) m |= 1ull << i2;
                else          for (int i2 = 0; i2 < II; i2++)       m |= 1ull << i2;
            }
            if (m == 0ull && !isalpha) {
                int sp = 1;
                while (s_pcnt[dir][sp] >= PCAP) sp++;
                int rb = s_pcnt[dir][sp]++;
                s_pSS[dir][np] = (short)sp;
                s_pRec[dir][np++] = 31 | (tgt << 5) | (1 << 11) | (rb << 12);
                finish[tgt] = sp;
                if (sp > maxss) maxss = sp;
                continue;
            }
            int slot = 0;
            for (int q = 1; q < NSLOT; q++)
                if (slotFree[q] < slotFree[slot]) slot = q;
            int s = slotFree[slot] - 1;
            int first = 1;
            unsigned long long mm = m;
            while (mm) {
                int j;
                if (dir) { j = 63 - __clzll((long long)mm); mm &= ~(1ull << j); }
                else     { j = __ffsll((long long)mm) - 1;  mm &= mm - 1; }
                int smin = s + 1;
                int fj = finish[j] + 1;
                if (fj > smin) smin = fj;
                s = smin;
                while (s_ecnt[dir][s] >= ECAP) s++;
                int sb = s_ecnt[dir][s]++;
                s_eSS[dir][ne] = (short)s;
                s_eRec[dir][ne++] = slot | (j << 5) | (first << 11) | (sb << 12);
                first = 0;
            }
            int sp = s + 1;
            while (s_pcnt[dir][sp] >= PCAP) sp++;
            int rb = s_pcnt[dir][sp]++;
            s_pSS[dir][np] = (short)sp;
            s_pRec[dir][np++] = slot | (tgt << 5) | (rb << 12) | ((isalpha ? 1 : 0) << 14);
            if (!isalpha) finish[tgt] = sp;
            slotFree[slot] = sp;
            if (sp > maxss) maxss = sp;
        }

        // counting sort to global
        int off = 0;
        for (int s2 = 0; s2 < MAXSS; s2++) { g_eoff[dir][s2] = off; off += s_ecnt[dir][s2]; }
        g_eoff[dir][MAXSS] = off;
        off = 0;
        for (int s2 = 0; s2 < MAXSS; s2++) { g_poff[dir][s2] = off; off += s_pcnt[dir][s2]; }
        g_poff[dir][MAXSS] = off;
        for (int e = 0; e < ne; e++) {
            int s2 = s_eSS[dir][e];
            g_erec[dir][g_eoff[dir][s2] + s_ecur[dir][s2]++] = s_eRec[dir][e];
        }
        for (int p = 0; p < np; p++) {
            int s2 = s_pSS[dir][p];
            g_prec[dir][g_poff[dir][s2] + s_pcur[dir][s2]++] = s_pRec[dir][p];
        }
        s_nssv[dir] = maxss + 1;
    }
    __syncthreads();
    if (t == 0) g_nss = (s_nssv[0] > s_nssv[1] ? s_nssv[0] : s_nssv[1]);
}

// ============================ phase 1: wavefront execution ============================
__global__ void __launch_bounds__(NT, 1)
phase1_kernel(const float* z, const float* dz, const float* has,
              const float* Wih_f, const float* Whh_f, const float* bih_f, const float* bhh_f,
              const float* Wih_b, const float* Whh_b, const float* bih_b, const float* bhh_b,
              const float* Wf, const float* bf, const float* Wb, const float* bb,
              const float* Wu)
{
    extern __shared__ float sm[];
    const int t = threadIdx.x;
    const int warp = t >> 5, lane = t & 31;
    const int bg = blockIdx.x;
    const int row0 = bg * ROWS;

    // GEMM role (warps 0..11): dir = warp/6, role = warp%6 -> gate, output lane
    const int gdir = warp / 6;
    const int grole = warp % 6;
    const int gg = grole % 3;
    const int go = (grole / 3) * 32 + lane;
    const bool gemmW = (warp < 12) && (go < SS);

    // Whh row in registers
    unsigned long long wp[30];
    if (gemmW) {
        const float* wsrc = (gdir ? Whh_b : Whh_f) + ((size_t)gg * SS + go) * SS;
#pragma unroll
        for (int q = 0; q < 30; q++)
            wp[q] = *(const unsigned long long*)(wsrc + 2 * q);
    }

    // ---- stage smem ----
    for (int idx = t; idx < 2 * 180 * SS; idx += NT) {
        int d = idx / (180 * SS), r = idx % (180 * SS);
        sm[OFF_WIH + idx] = (d ? Wih_b : Wih_f)[r];
    }
    for (int idx = t; idx < 2 * 180; idx += NT) {
        int d = idx / 180, r = idx % 180;
        sm[OFF_BHH + idx] = (d ? bhh_b : bhh_f)[r];
        sm[OFF_BIH + idx] = (d ? bih_b : bih_f)[r];
    }
    for (int idx = t; idx < 2 * SS; idx += NT) {
        int d = idx / SS, r = idx % SS;
        sm[OFF_BP + idx] = (d ? bb : bf)[r];
    }
    for (int idx = t; idx < ROWS * NN; idx += NT)
        sm[OFF_HAS + idx] = has[(size_t)(row0 + idx / NN) * NN + (idx % NN)];
    for (int idx = t; idx < 2 * NROLE * SS; idx += NT) {
        int d = idx / (NROLE * SS), rr = (idx / SS) % NROLE, s2 = idx % SS;
        sm[OFF_WU + idx] = Wu[rr * 2 * SS + d * SS + s2];
    }
    __syncthreads();

    const int nss = g_nss;

    for (int s = 0; s < nss; s++) {
        const int e0f = g_eoff[0][s], e1f = g_eoff[0][s + 1];
        const int e0b = g_eoff[1][s], e1b = g_eoff[1][s + 1];
        const int p0f = g_poff[0][s], p1f = g_poff[0][s + 1];
        const int p0b = g_poff[1][s], p1b = g_poff[1][s + 1];

        // ================= phase A =================
        if (warp < 12) {
            // edge GEMMs, fixed role, loop over this dir's edges
            const int e0 = gdir ? e0b : e0f;
            const int e1 = gdir ? e1b : e1f;
            const float* gi_g = gdir ? g_gi_b : g_gi_f;
            for (int e = e0; e < e1; e++) {
                const int rec = g_erec[gdir][e];
                if (!gemmW) continue;
                const int slot = rec & 31;
                const int node = (rec >> 5) & 63;
                const int hz = (rec >> 11) & 1;
                const int sbuf = (rec >> 12) & 7;
                const float4 gi = *(const float4*)(gi_g +
                    ((((size_t)node * NBG + bg) * 3 + gg) * SS + go) * 4);
                unsigned long long a0 = 0, a1 = 0, a2 = 0, a3 = 0;
                if (!hz) {
                    const int hb = OFF_HBS + (gdir * NSLOT + slot) * 256;
#pragma unroll
                    for (int q = 0; q < 15; q++) {
                        ulonglong2 h0 = *(const ulonglong2*)&sm[hb + 0 * 64 + 4 * q];
                        ulonglong2 h1 = *(const ulonglong2*)&sm[hb + 1 * 64 + 4 * q];
                        ulonglong2 h2 = *(const ulonglong2*)&sm[hb + 2 * 64 + 4 * q];
                        ulonglong2 h3 = *(const ulonglong2*)&sm[hb + 3 * 64 + 4 * q];
                        fma2(a0, wp[2 * q], h0.x); fma2(a0, wp[2 * q + 1], h0.y);
                        fma2(a1, wp[2 * q], h1.x); fma2(a1, wp[2 * q + 1], h1.y);
                        fma2(a2, wp[2 * q], h2.x); fma2(a2, wp[2 * q + 1], h2.y);
                        fma2(a3, wp[2 * q], h3.x); fma2(a3, wp[2 * q + 1], h3.y);
                    }
                }
                const float bh = sm[OFF_BHH + gdir * 180 + gg * SS + go];
                float v0 = lo32(a0) + hi32(a0) + bh;
                float v1 = lo32(a1) + hi32(a1) + bh;
                float v2 = lo32(a2) + hi32(a2) + bh;
                float v3 = lo32(a3) + hi32(a3) + bh;
                const int Sb = OFF_SBUF + (gdir * ECAP + sbuf) * 960;
                if (gg < 2) {
                    sm[Sb + gg * 240 + 0 * SS + go] = v0 + gi.x;
                    sm[Sb + gg * 240 + 1 * SS + go] = v1 + gi.y;
                    sm[Sb + gg * 240 + 2 * SS + go] = v2 + gi.z;
                    sm[Sb + gg * 240 + 3 * SS + go] = v3 + gi.w;
                } else {
                    sm[Sb + 2 * 240 + 0 * SS + go] = v0;
                    sm[Sb + 2 * 240 + 1 * SS + go] = v1;
                    sm[Sb + 2 * 240 + 2 * SS + go] = v2;
                    sm[Sb + 2 * 240 + 3 * SS + go] = v3;
                    sm[Sb + 3 * 240 + 0 * SS + go] = gi.x;
                    sm[Sb + 3 * 240 + 1 * SS + go] = gi.y;
                    sm[Sb + 3 * 240 + 2 * SS + go] = gi.z;
                    sm[Sb + 3 * 240 + 3 * SS + go] = gi.w;
                }
            }
        } else {
            // projections / alpha stores (warps 12-13, 64 lanes)
            const int local = t - 384;
            for (int d = 0; d < 2; d++) {
                const int p0 = d ? p0b : p0f;
                const int p1 = d ? p1b : p1f;
                for (int p = p0; p < p1; p++) {
                    const int rec = g_prec[d][p];
                    const int slot = rec & 31;
                    const int hz = (rec >> 11) & 1;
                    const int rbuf = (rec >> 12) & 3;
                    const int isalpha = (rec >> 14) & 1;
                    if (isalpha) {
                        float* ag = d ? g_alpha_b : g_alpha_f;
                        const int hs = OFF_HSB + (d * NSLOT + slot) * 240;
                        for (int idx = local; idx < 240; idx += 64) {
                            int o = idx >> 2, b = idx & 3;
                            ag[(size_t)(row0 + b) * SS + o] = sm[hs + idx];
                        }
                    } else {
                        const float* Wp = d ? Wb : Wf;
                        const int hs = OFF_HSB + (d * NSLOT + slot) * 240;
                        const int zb = OFF_ZBUF + (d * PCAP + rbuf) * 80;
                        for (int idx = local; idx < 240; idx += 64) {
                            int o = idx >> 2, b = idx & 3;
                            float acc = sm[OFF_BP + d * SS + o];
                            const float4* wrow = (const float4*)(Wp + o * 80);
                            if (!hz) {
#pragma unroll
                                for (int q = 0; q < 15; q++) {
                                    float4 w4 = wrow[q];
                                    acc = fmaf(w4.x, sm[hs + (4 * q + 0) * 4 + b], acc);
                                    acc = fmaf(w4.y, sm[hs + (4 * q + 1) * 4 + b], acc);
                                    acc = fmaf(w4.z, sm[hs + (4 * q + 2) * 4 + b], acc);
                                    acc = fmaf(w4.w, sm[hs + (4 * q + 3) * 4 + b], acc);
                                }
                            }
#pragma unroll
                            for (int q = 0; q < 5; q++) {
                                float4 w4 = wrow[15 + q];
                                int u = 4 * q;
                                float x0 = (u < SEX)     ? sm[zb + b * SEX + u]           : sm[zb + 40 + b * SEX + u - SEX];
                                float x1 = (u + 1 < SEX) ? sm[zb + b * SEX + u + 1]       : sm[zb + 40 + b * SEX + u + 1 - SEX];
                                float x2 = (u + 2 < SEX) ? sm[zb + b * SEX + u + 2]       : sm[zb + 40 + b * SEX + u + 2 - SEX];
                                float x3 = (u + 3 < SEX) ? sm[zb + b * SEX + u + 3]       : sm[zb + 40 + b * SEX + u + 3 - SEX];
                                acc = fmaf(w4.x, x0, acc);
                                acc = fmaf(w4.y, x1, acc);
                                acc = fmaf(w4.z, x2, acc);
                                acc = fmaf(w4.w, x3, acc);
                            }
                            sm[OFF_RHO + (d * PCAP + rbuf) * 240 + idx] = d ? acc : tanh_f(acc);
                        }
                    }
                }
            }
        }
        __syncthreads();

        // ================= phase B =================
        // 1) activations for all edges this superstep
        const int nEf = e1f - e0f, nEb = e1b - e0b;
        const int nE = nEf + nEb;
        for (int idx = t; idx < nE * 240; idx += NT) {
            const int e = idx / 240, l = idx - e * 240;
            const int d = (e < nEf) ? 0 : 1;
            const int rec = g_erec[d][d ? (e0b + e - nEf) : (e0f + e)];
            const int slot = rec & 31;
            const int node = (rec >> 5) & 63;
            const int hz = (rec >> 11) & 1;
            const int sbuf = (rec >> 12) & 7;
            const int b = l / SS, o = l - b * SS;
            const int Sb = OFF_SBUF + (d * ECAP + sbuf) * 960;
            float r  = sigm(sm[Sb + l]);
            float zg = sigm(sm[Sb + 240 + l]);
            float nv = tanh_f(fmaf(r, sm[Sb + 480 + l], sm[Sb + 720 + l]));
            const int hb = OFF_HBS + (d * NSLOT + slot) * 256;
            float hold = hz ? 0.f : sm[hb + b * 64 + o];
            float hnew = (1.f - zg) * nv + zg * hold;
            float blend = sm[OFF_HAS + b * 64 + node];
            float res = hold + blend * (hnew - hold);
            sm[hb + b * 64 + o] = res;
            sm[OFF_HSB + (d * NSLOT + slot) * 240 + o * 4 + b] = res;
        }
        // 2) gi + psi for this superstep's projections
        const int nPf = p1f - p0f, nPb = p1b - p0b;
        const int nP = nPf + nPb;
        for (int idx = t; idx < nP * 192; idx += NT) {
            const int p = idx / 192, l = idx - p * 192;
            const int d = (p < nPf) ? 0 : 1;
            const int rec = g_prec[d][d ? (p0b + p - nPf) : (p0f + p)];
            if ((rec >> 14) & 1) continue;            // alpha: no gi
            const int tgt = (rec >> 5) & 63;
            const int rbuf = (rec >> 12) & 3;
            const int rb = OFF_RHO + (d * PCAP + rbuf) * 240;
            if (l < 180) {
                unsigned long long a01 = splat2(sm[OFF_BIH + d * 180 + l]);
                unsigned long long a23 = a01;
                const float4* wrow = (const float4*)&sm[OFF_WIH + d * 10800 + l * SS];
#pragma unroll
                for (int q = 0; q < 15; q++) {
                    float4 w4 = wrow[q];
                    ulonglong2 r0 = *(const ulonglong2*)&sm[rb + (4 * q + 0) * 4];
                    ulonglong2 r1 = *(const ulonglong2*)&sm[rb + (4 * q + 1) * 4];
                    ulonglong2 r2 = *(const ulonglong2*)&sm[rb + (4 * q + 2) * 4];
                    ulonglong2 r3 = *(const ulonglong2*)&sm[rb + (4 * q + 3) * 4];
                    unsigned long long wx = splat2(w4.x), wy = splat2(w4.y);
                    unsigned long long wz = splat2(w4.z), ww = splat2(w4.w);
                    fma2(a01, wx, r0.x); fma2(a23, wx, r0.y);
                    fma2(a01, wy, r1.x); fma2(a23, wy, r1.y);
                    fma2(a01, wz, r2.x); fma2(a23, wz, r2.y);
                    fma2(a01, ww, r3.x); fma2(a23, ww, r3.y);
                }
                const int g2 = l / SS, o2 = l - g2 * SS;
                float* gi_g = d ? g_gi_b : g_gi_f;
                *(float4*)(gi_g + ((((size_t)tgt * NBG + bg) * 3 + g2) * SS + o2) * 4) =
                    make_float4(lo32(a01), hi32(a01), lo32(a23), hi32(a23));
            } else if (l < 180 + NROLE) {
                const int r = l - 180;
                unsigned long long a01 = 0, a23 = 0;
#pragma unroll 10
                for (int s2 = 0; s2 < SS; s2++) {
                    unsigned long long w = splat2(sm[OFF_WU + d * 420 + r * SS + s2]);
                    ulonglong2 rr = *(const ulonglong2*)&sm[rb + s2 * 4];
                    fma2(a01, w, rr.x);
                    fma2(a23, w, rr.y);
                }
                float* psi_g = d ? g_psi_b : g_psi_f;
                psi_g[((size_t)(row0 + 0) * NROLE + r) * NN + tgt] = lo32(a01);
                psi_g[((size_t)(row0 + 1) * NROLE + r) * NN + tgt] = hi32(a01);
                psi_g[((size_t)(row0 + 2) * NROLE + r) * NN + tgt] = lo32(a23);
                psi_g[((size_t)(row0 + 3) * NROLE + r) * NN + tgt] = hi32(a23);
            }
        }
        // 3) z prestage for projections at superstep s+1
        if (s + 1 < nss) {
            const int q0f = g_poff[0][s + 1], q1f = g_poff[0][s + 2];
            const int q0b = g_poff[1][s + 1], q1b = g_poff[1][s + 2];
            const int nZf = q1f - q0f, nZ = nZf + (q1b - q0b);
            for (int idx = t; idx < nZ * 80; idx += NT) {
                const int p = idx / 80, l = idx - p * 80;
                const int d = (p < nZf) ? 0 : 1;
                const int rec = g_prec[d][d ? (q0b + p - nZf) : (q0f + p)];
                if ((rec >> 14) & 1) continue;        // alpha
                const int tgt = (rec >> 5) & 63;
                const int rbuf = (rec >> 12) & 3;
                const int lb = (l < 40) ? l : l - 40;
                const int b = lb / SEX, u = lb - b * SEX;
                const float* src = (l < 40) ? z : dz;
                sm[OFF_ZBUF + (d * PCAP + rbuf) * 80 + l] =
                    src[((size_t)(row0 + b)) * NN * SEX + (size_t)tgt * SEX + u];
            }
        }
        __syncthreads();
    }
}

// ---- phase 2: heads + psi assembly + softmaxes ----
#define P2NT 192
#define P2_AF 0
#define P2_AB 240
#define P2_HAS 480
#define P2_OMG 736
#define P2_PSI 768
#define P2_FLOATS (P2_PSI + ROWS * NROLE * NN)

__global__ void __launch_bounds__(P2NT)
phase2_kernel(const float* has, const float* Wa, const float* ba,
              const float* Wc, const float* bc, const float* bu,
              float* out)
{
    __shared__ float s2[P2_FLOATS];
    const int t = threadIdx.x;
    const int row0 = blockIdx.x * ROWS;

    for (int idx = t; idx < SS * ROWS; idx += P2NT) {
        int s = idx >> 2, b = idx & 3;
        s2[P2_AF + idx] = g_alpha_f[(size_t)(row0 + b) * SS + s];
        s2[P2_AB + idx] = g_alpha_b[(size_t)(row0 + b) * SS + s];
    }
    for (int idx = t; idx < ROWS * NN; idx += P2NT)
        s2[P2_HAS + idx] = has[(size_t)(row0 + idx / NN) * NN + (idx % NN)];
    __syncthreads();

    if (t < ROWS * NACT) {
        int b = t / NACT, a = t % NACT;
        float acc = ba[a];
#pragma unroll
        for (int s = 0; s < SS; s++) {
            acc = fmaf(Wa[a * 2 * SS + s],      s2[P2_AF + s * 4 + b], acc);
            acc = fmaf(Wa[a * 2 * SS + SS + s], s2[P2_AB + s * 4 + b], acc);
        }
        s2[P2_OMG + t] = acc;
    } else if (t < ROWS * NACT + ROWS) {
        int b = t - ROWS * NACT;
        float acc = bc[0];
#pragma unroll
        for (int s = 0; s < SS; s++) {
            acc = fmaf(Wc[s],      s2[P2_AF + s * 4 + b], acc);
            acc = fmaf(Wc[SS + s], s2[P2_AB + s * 4 + b], acc);
        }
        out[(size_t)BATCH * NACT + (size_t)BATCH * NROLE * NN + row0 + b] = acc;
    }

    for (int idx = t; idx < ROWS * NROLE * NN; idx += P2NT) {
        int n = idx % NN;
        int r = (idx / NN) % NROLE;
        int b = idx / (NROLE * NN);
        size_t gg = ((size_t)(row0 + b) * NROLE + r) * NN + n;
        float v = g_psi_f[gg] + g_psi_b[gg] + bu[r];
        float m = s2[P2_HAS + b * NN + n];
        s2[P2_PSI + idx] = m * v - 60.f * (1.f - m);
    }
    __syncthreads();

    if (t < ROWS) {
        float mx = -1e30f;
        for (int a = 0; a < NACT; a++) mx = fmaxf(mx, s2[P2_OMG + t * NACT + a]);
        float e[NACT], ssum = 0.f;
        for (int a = 0; a < NACT; a++) {
            e[a] = __expf(s2[P2_OMG + t * NACT + a] - mx);
            ssum += e[a];
        }
        float inv = __fdividef(1.f, ssum);
        for (int a = 0; a < NACT; a++) out[(size_t)(row0 + t) * NACT + a] = e[a] * inv;
    }

    for (int p0 = t; p0 < ROWS * NROLE; p0 += P2NT) {
        int b = p0 / NROLE, r = p0 % NROLE;
        float* rowp = &s2[P2_PSI + (b * NROLE + r) * NN];
        float mx = -1e30f;
        for (int n = 0; n < NN; n++) mx = fmaxf(mx, rowp[n]);
        float ssum = 0.f;
        for (int n = 0; n < NN; n++) { float e = __expf(rowp[n] - mx); rowp[n] = e; ssum += e; }
        float inv = __fdividef(1.f, ssum);
        float* op = out + (size_t)BATCH * NACT + (size_t)(row0 + b) * NROLE * NN + (size_t)r * NN;
        for (int n = 0; n < NN; n++) op[n] = rowp[n] * inv;
    }
}

extern "C" void kernel_launch(void* const* d_in, const int* in_sizes, int n_in,
                              void* d_out, int out_size)
{
    setup_kernel<<<1, 64>>>((const int*)d_in[3]);
    cudaFuncSetAttribute(phase1_kernel, cudaFuncAttributeMaxDynamicSharedMemorySize, SMEM_BYTES);
    phase1_kernel<<<NBG, NT, SMEM_BYTES>>>(
        (const float*)d_in[0], (const float*)d_in[1], (const float*)d_in[2],
        (const float*)d_in[4], (const float*)d_in[5], (const float*)d_in[6], (const float*)d_in[7],
        (const float*)d_in[8], (const float*)d_in[9], (const float*)d_in[10], (const float*)d_in[11],
        (const float*)d_in[12], (const float*)d_in[13], (const float*)d_in[14], (const float*)d_in[15],
        (const float*)d_in[20]);
    phase2_kernel<<<NBG, P2NT>>>(
        (const float*)d_in[2],
        (const float*)d_in[16], (const float*)d_in[17], (const float*)d_in[18], (const float*)d_in[19],
        (const float*)d_in[21], (float*)d_out);
}

// round 15
// speedup vs baseline: 2.0643x; 2.0643x over previous
#include <cuda_runtime.h>

#define NN 64
#define SS 60
#define GG 180
#define BATCH 512
#define SEX 10
#define ROWS 4
#define NT 256
#define NBG (BATCH / ROWS)
#define NACT 5
#define NROLE 7
#define OO 8
#define II 8

// ---- phase-1 shared memory layout (float offsets) ----
#define OFF_WIH  0          // 180*60
#define OFF_BIH  10800      // 180
#define OFF_BHH  10980      // 180 [g*60+o]
#define OFF_BP   11160      // 60
#define OFF_HAS  11220      // [b][64] = 256
#define OFF_MASK 11476      // 64 ull = 128 floats
#define OFF_NEED 11604      // 64
#define OFF_WUH  11668      // 7*60
#define OFF_HBS0 12088      // H ping  [b][64]
#define OFF_HBS1 12344      // H pong  [b][64]
#define OFF_HSB0 12600      // H ping  [s][4]
#define OFF_HSB1 12840      // H pong  [s][4]
#define OFF_S    13080      // 4 x [b*60+o] = 960  (r, z, nA, nG)
#define OFF_RHO  14040      // [s][4]
#define OFF_ZI   14280
#define OFF_DZI  14320
#define SMEM_FLOATS 14360
#define SMEM_BYTES (SMEM_FLOATS * 4)

// ---- global scratch ----
// gi layout: [node][bg][gate][o][4 rows]
__device__ float g_gi_f[(size_t)NN * NBG * 3 * SS * 4];
__device__ float g_gi_b[(size_t)NN * NBG * 3 * SS * 4];
__device__ float g_alpha_f[(size_t)BATCH * SS];
__device__ float g_alpha_b[(size_t)BATCH * SS];
__device__ float g_psi_f[(size_t)BATCH * NROLE * NN];
__device__ float g_psi_b[(size_t)BATCH * NROLE * NN];

__device__ __forceinline__ float sigm(float x) {
    return __fdividef(1.f, 1.f + __expf(-x));
}
__device__ __forceinline__ float tanh_f(float x) {
    float e = __expf(2.f * x);
    return 1.f - __fdividef(2.f, e + 1.f);
}
__device__ __forceinline__ void fma2(unsigned long long& d, unsigned long long a,
                                     unsigned long long b) {
    asm("fma.rn.f32x2 %0, %1, %2, %0;" : "+l"(d) : "l"(a), "l"(b));
}
__device__ __forceinline__ unsigned long long splat2(float w) {
    unsigned long long r;
    asm("mov.b64 %0, {%1, %1};" : "=l"(r) : "f"(w));
    return r;
}
__device__ __forceinline__ float lo32(unsigned long long v) {
    return __uint_as_float((unsigned)v);
}
__device__ __forceinline__ float hi32(unsigned long long v) {
    return __uint_as_float((unsigned)(v >> 32));
}
__device__ __forceinline__ void prefetchL1(const float* p) {
    asm volatile("prefetch.global.L1 [%0];" :: "l"(p));
}

// One GRU edge step: gate-split GEMM (6 warps, weights in regs) + exchange + act.
// wp: 30 register w-pairs over s for this lane's (gate g, output o).
__device__ __forceinline__ void gru_step(int node, const float* gi4, bool& hz,
                                         int bg, bool gemmActive, int g, int o,
                                         const unsigned long long* wp,
                                         int curBS, int nxtBS, int nxtSB)
{
    extern __shared__ float sm[];
    const int t = threadIdx.x;
    if (gemmActive) {
        const float4 gi = *(const float4*)(gi4 +
            ((((size_t)node * NBG + bg) * 3 + g) * SS + o) * 4);
        unsigned long long acc0 = 0, acc1 = 0, acc2 = 0, acc3 = 0;
        if (!hz) {
#pragma unroll
            for (int q = 0; q < 15; q++) {
                ulonglong2 h0 = *(const ulonglong2*)&sm[curBS + 0 * 64 + 4 * q];
                ulonglong2 h1 = *(const ulonglong2*)&sm[curBS + 1 * 64 + 4 * q];
                ulonglong2 h2 = *(const ulonglong2*)&sm[curBS + 2 * 64 + 4 * q];
                ulonglong2 h3 = *(const ulonglong2*)&sm[curBS + 3 * 64 + 4 * q];
                fma2(acc0, wp[2 * q], h0.x); fma2(acc0, wp[2 * q + 1], h0.y);
                fma2(acc1, wp[2 * q], h1.x); fma2(acc1, wp[2 * q + 1], h1.y);
                fma2(acc2, wp[2 * q], h2.x); fma2(acc2, wp[2 * q + 1], h2.y);
                fma2(acc3, wp[2 * q], h3.x); fma2(acc3, wp[2 * q + 1], h3.y);
            }
        }
        float bh = sm[OFF_BHH + g * SS + o];
        float a0 = lo32(acc0) + hi32(acc0) + bh;
        float a1 = lo32(acc1) + hi32(acc1) + bh;
        float a2 = lo32(acc2) + hi32(acc2) + bh;
        float a3 = lo32(acc3) + hi32(acc3) + bh;
        if (g < 2) {
            sm[OFF_S + g * 240 + 0 * 60 + o] = a0 + gi.x;
            sm[OFF_S + g * 240 + 1 * 60 + o] = a1 + gi.y;
            sm[OFF_S + g * 240 + 2 * 60 + o] = a2 + gi.z;
            sm[OFF_S + g * 240 + 3 * 60 + o] = a3 + gi.w;
        } else {
            sm[OFF_S + 2 * 240 + 0 * 60 + o] = a0;
            sm[OFF_S + 2 * 240 + 1 * 60 + o] = a1;
            sm[OFF_S + 2 * 240 + 2 * 60 + o] = a2;
            sm[OFF_S + 2 * 240 + 3 * 60 + o] = a3;
            sm[OFF_S + 3 * 240 + 0 * 60 + o] = gi.x;
            sm[OFF_S + 3 * 240 + 1 * 60 + o] = gi.y;
            sm[OFF_S + 3 * 240 + 2 * 60 + o] = gi.z;
            sm[OFF_S + 3 * 240 + 3 * 60 + o] = gi.w;
        }
    }
    __syncthreads();
    if (t < 240) {
        int b = t / 60, o2 = t % 60;
        float r  = sigm(sm[OFF_S + 0 * 240 + t]);
        float zg = sigm(sm[OFF_S + 1 * 240 + t]);
        float nv = tanh_f(fmaf(r, sm[OFF_S + 2 * 240 + t], sm[OFF_S + 3 * 240 + t]));
        float hold = hz ? 0.f : sm[curBS + b * 64 + o2];
        float hnew = (1.f - zg) * nv + zg * hold;
        float blend = sm[OFF_HAS + b * 64 + node];
        float res = hold + blend * (hnew - hold);
        sm[nxtBS + b * 64 + o2] = res;
        sm[nxtSB + o2 * 4 + b] = res;
    }
    __syncthreads();
    hz = false;
}

// rho_i = act([h, z_i, dz_i] @ Wp^T + bp) -> smem RHO [s][4]. Wp from global.
__device__ __forceinline__ void project(int node, const float* z, const float* dz,
                                        const float* Wp, bool isfwd, bool hz,
                                        int row0, int curSB)
{
    extern __shared__ float sm[];
    const int t = threadIdx.x;
    if (t < 2 * ROWS * SEX) {
        int which = t / 40;
        int loc = t % 40;
        int b = loc / SEX, u = loc % SEX;
        const float* src = which ? dz : z;
        sm[(which ? OFF_DZI : OFF_ZI) + loc] =
            src[((size_t)(row0 + b)) * NN * SEX + (size_t)node * SEX + u];
    }
    __syncthreads();
    if (t < SS * ROWS) {
        int o = t >> 2, b = t & 3;
        float acc = sm[OFF_BP + o];
        const float4* wrow = (const float4*)(Wp + o * 80);
        if (!hz) {
#pragma unroll
            for (int q = 0; q < SS / 4; q++) {
                float4 w4 = wrow[q];
                acc = fmaf(w4.x, sm[curSB + (4 * q + 0) * 4 + b], acc);
                acc = fmaf(w4.y, sm[curSB + (4 * q + 1) * 4 + b], acc);
                acc = fmaf(w4.z, sm[curSB + (4 * q + 2) * 4 + b], acc);
                acc = fmaf(w4.w, sm[curSB + (4 * q + 3) * 4 + b], acc);
            }
        }
#pragma unroll
        for (int q = 0; q < (2 * SEX) / 4; q++) {
            float4 w4 = wrow[SS / 4 + q];
            int u = 4 * q;
            float v0 = (u < SEX)     ? sm[OFF_ZI + b * SEX + u]     : sm[OFF_DZI + b * SEX + u - SEX];
            float v1 = (u + 1 < SEX) ? sm[OFF_ZI + b * SEX + u + 1] : sm[OFF_DZI + b * SEX + u + 1 - SEX];
            float v2 = (u + 2 < SEX) ? sm[OFF_ZI + b * SEX + u + 2] : sm[OFF_DZI + b * SEX + u + 2 - SEX];
            float v3 = (u + 3 < SEX) ? sm[OFF_ZI + b * SEX + u + 3] : sm[OFF_DZI + b * SEX + u + 3 - SEX];
            acc = fmaf(w4.x, v0, acc);
            acc = fmaf(w4.y, v1, acc);
            acc = fmaf(w4.z, v2, acc);
            acc = fmaf(w4.w, v3, acc);
        }
        sm[OFF_RHO + t] = isfwd ? tanh_f(acc) : acc;
    }
    __syncthreads();
}

// gi (lanes 0..179, optional, gate-major layout) + psi (lanes 180..186).
__device__ __forceinline__ void gi_psi_step(int node, float* gi4, float* psi_g,
                                            bool doGi, int row0, int bg)
{
    extern __shared__ float sm[];
    const int t = threadIdx.x;
    if (t < GG) {
        if (doGi) {
            unsigned long long a01 = splat2(sm[OFF_BIH + t]);
            unsigned long long a23 = a01;
            const float4* wrow = (const float4*)&sm[OFF_WIH + t * SS];
#pragma unroll
            for (int q = 0; q < SS / 4; q++) {
                float4 w4 = wrow[q];
                ulonglong2 r0 = *(const ulonglong2*)&sm[OFF_RHO + (4 * q + 0) * 4];
                ulonglong2 r1 = *(const ulonglong2*)&sm[OFF_RHO + (4 * q + 1) * 4];
                ulonglong2 r2 = *(const ulonglong2*)&sm[OFF_RHO + (4 * q + 2) * 4];
                ulonglong2 r3 = *(const ulonglong2*)&sm[OFF_RHO + (4 * q + 3) * 4];
                unsigned long long wx = splat2(w4.x), wy = splat2(w4.y);
                unsigned long long wz = splat2(w4.z), ww = splat2(w4.w);
                fma2(a01, wx, r0.x); fma2(a23, wx, r0.y);
                fma2(a01, wy, r1.x); fma2(a23, wy, r1.y);
                fma2(a01, wz, r2.x); fma2(a23, wz, r2.y);
                fma2(a01, ww, r3.x); fma2(a23, ww, r3.y);
            }
            int g = t / SS, o = t % SS;
            float4* dst = (float4*)(gi4 + ((((size_t)node * NBG + bg) * 3 + g) * SS + o) * 4);
            *dst = make_float4(lo32(a01), hi32(a01), lo32(a23), hi32(a23));
        }
    } else if (t < GG + NROLE) {
        int r = t - GG;
        unsigned long long a01 = 0, a23 = 0;
#pragma unroll 10
        for (int s = 0; s < SS; s++) {
            unsigned long long w = splat2(sm[OFF_WUH + r * SS + s]);
            ulonglong2 rr = *(const ulonglong2*)&sm[OFF_RHO + s * 4];
            fma2(a01, w, rr.x);
            fma2(a23, w, rr.y);
        }
        psi_g[((size_t)(row0 + 0) * NROLE + r) * NN + node] = lo32(a01);
        psi_g[((size_t)(row0 + 1) * NROLE + r) * NN + node] = hi32(a01);
        psi_g[((size_t)(row0 + 2) * NROLE + r) * NN + node] = lo32(a23);
        psi_g[((size_t)(row0 + 3) * NROLE + r) * NN + node] = hi32(a23);
    }
    __syncthreads();
}

__global__ void __launch_bounds__(NT, 2)
phase1_kernel(const float* z, const float* dz, const float* has, const int* adj,
              const float* Wih_f, const float* Whh_f, const float* bih_f, const float* bhh_f,
              const float* Wih_b, const float* Whh_b, const float* bih_b, const float* bhh_b,
              const float* Wf, const float* bf, const float* Wb, const float* bb,
              const float* Wu)
{
    extern __shared__ float sm[];
    const int t = threadIdx.x;
    const int warp = t >> 5, lane = t & 31;
    const int bg = blockIdx.x;
    const int row0 = bg * ROWS;
    const int dir = blockIdx.y;

    const float* Whh = dir ? Whh_b : Whh_f;
    const float* Wih = dir ? Wih_b : Wih_f;
    const float* Wp  = dir ? Wb    : Wf;
    const float* bhh = dir ? bhh_b : bhh_f;
    const float* bih = dir ? bih_b : bih_f;
    const float* bp  = dir ? bb    : bf;
    float* gi4     = dir ? g_gi_b    : g_gi_f;
    float* alpha_g = dir ? g_alpha_b : g_alpha_f;
    float* psi_g   = dir ? g_psi_b   : g_psi_f;

    // GEMM warp role (arithmetic, avoids local-mem tables):
    // fwd uses warps {0,1,2,3,4,7}; bwd uses {0,1,2,3,5,6} -> 3 GEMM warps/SMSP
    // when a fwd CTA and bwd CTA co-reside.
    int role;
    if (dir == 0) role = (warp < 5) ? warp : (warp == 7 ? 5 : -1);
    else          role = (warp < 4) ? warp : (warp == 5 ? 4 : (warp == 6 ? 5 : -1));
    const int g = (role >= 0) ? role % 3 : 0;
    const int o = (role >= 0) ? (role / 3) * 32 + lane : 0;
    const bool gemmActive = (role >= 0) && (o < SS);

    // Whh row for this lane in registers (30 x f32x2 pairs over s).
    unsigned long long wp[30];
    if (gemmActive) {
        const float* wsrc = Whh + ((size_t)g * SS + o) * SS;
#pragma unroll
        for (int q = 0; q < 30; q++)
            wp[q] = *(const unsigned long long*)(wsrc + 2 * q);
    }

    // ---- stage smem ----
    for (int idx = t; idx < GG * SS; idx += NT) sm[OFF_WIH + idx] = Wih[idx];
    for (int idx = t; idx < GG; idx += NT) {
        sm[OFF_BIH + idx] = bih[idx];
        sm[OFF_BHH + idx] = bhh[idx];
    }
    if (t < SS) sm[OFF_BP + t] = bp[t];
    for (int idx = t; idx < ROWS * NN; idx += NT)
        sm[OFF_HAS + idx] = has[(size_t)(row0 + idx / NN) * NN + (idx % NN)];
    for (int idx = t; idx < NROLE * SS; idx += NT) {
        int r = idx / SS, s = idx % SS;
        sm[OFF_WUH + idx] = Wu[r * 2 * SS + dir * SS + s];
    }
    if (t < NN) {
        unsigned long long pm = 0ull, sk = 0ull;
        for (int j = 0; j < NN; j++) {
            if (adj[j * NN + t]) pm |= 1ull << j;   // predecessors of t
            if (adj[t * NN + j]) sk |= 1ull << j;   // successors of t
        }
        ((unsigned long long*)&sm[OFF_MASK])[t] = dir ? sk : pm;
        bool need = dir ? (pm != 0ull || t < II) : (sk != 0ull || t >= NN - OO);
        ((int*)&sm[OFF_NEED])[t] = need ? 1 : 0;
    }
    __syncthreads();

    const unsigned long long* mask = (const unsigned long long*)&sm[OFF_MASK];
    const int* need = (const int*)&sm[OFF_NEED];

    int curBS = OFF_HBS0, nxtBS = OFF_HBS1;
    int curSB = OFF_HSB0, nxtSB = OFF_HSB1;

    // ---- DAG pass ----
    for (int k = 0; k < NN; k++) {
        const int i = dir ? NN - 1 - k : k;
        bool hz = true;
        unsigned long long m = mask[i];

        // Prefetch: all gi lines this target's edges will read (safe — every
        // source node finished strictly before target i starts), plus the
        // z/dz lines the projection will read.
        if (gemmActive) {
            unsigned long long pf = m;
            while (pf) {
                int j;
                if (dir) { j = 63 - __clzll((long long)pf); pf &= ~(1ull << j); }
                else     { j = __ffsll((long long)pf) - 1;  pf &= pf - 1; }
                prefetchL1(gi4 + ((((size_t)j * NBG + bg) * 3 + g) * SS + o) * 4);
            }
        }
        if (t < 2 * ROWS * SEX) {
            int which = t / 40;
            int loc = t % 40;
            int b = loc / SEX, u = loc % SEX;
            const float* src = which ? dz : z;
            prefetchL1(src + ((size_t)(row0 + b)) * NN * SEX + (size_t)i * SEX + u);
        }

        while (m) {
            int j;
            if (dir) { j = 63 - __clzll((long long)m); m &= ~(1ull << j); }
            else     { j = __ffsll((long long)m) - 1;  m &= m - 1; }
            gru_step(j, gi4, hz, bg, gemmActive, g, o, wp, curBS, nxtBS, nxtSB);
            int tb = curBS; curBS = nxtBS; nxtBS = tb;
            int ts = curSB; curSB = nxtSB; nxtSB = ts;
        }
        project(i, z, dz, Wp, dir == 0, hz, row0, curSB);
        gi_psi_step(i, gi4, psi_g, need[i] != 0, row0, bg);
    }

    // ---- alpha scan ----
    {
        bool hz = true;
        if (gemmActive) {
#pragma unroll
            for (int k2 = 0; k2 < OO; k2++) {
                int an = dir ? (II - 1 - k2) : (NN - OO + k2);
                prefetchL1(gi4 + ((((size_t)an * NBG + bg) * 3 + g) * SS + o) * 4);
            }
        }
        for (int k2 = 0; k2 < OO; k2++) {
            int an = dir ? (II - 1 - k2) : (NN - OO + k2);
            gru_step(an, gi4, hz, bg, gemmActive, g, o, wp, curBS, nxtBS, nxtSB);
            int tb = curBS; curBS = nxtBS; nxtBS = tb;
            int ts = curSB; curSB = nxtSB; nxtSB = ts;
        }
        if (t < SS * ROWS) {
            int o2 = t >> 2, b = t & 3;
            alpha_g[(size_t)(row0 + b) * SS + o2] = sm[curSB + t];
        }
    }
}

// ---- phase 2: heads + psi assembly + softmaxes (tiny) ----
#define P2NT 192
#define P2_AF 0
#define P2_AB 240
#define P2_HAS 480
#define P2_OMG 736
#define P2_PSI 768
#define P2_FLOATS (P2_PSI + ROWS * NROLE * NN)

__global__ void __launch_bounds__(P2NT)
phase2_kernel(const float* has, const float* Wa, const float* ba,
              const float* Wc, const float* bc, const float* bu,
              float* out)
{
    __shared__ float s2[P2_FLOATS];
    const int t = threadIdx.x;
    const int row0 = blockIdx.x * ROWS;

    for (int idx = t; idx < SS * ROWS; idx += P2NT) {
        int s = idx >> 2, b = idx & 3;
        s2[P2_AF + idx] = g_alpha_f[(size_t)(row0 + b) * SS + s];
        s2[P2_AB + idx] = g_alpha_b[(size_t)(row0 + b) * SS + s];
    }
    for (int idx = t; idx < ROWS * NN; idx += P2NT)
        s2[P2_HAS + idx] = has[(size_t)(row0 + idx / NN) * NN + (idx % NN)];
    __syncthreads();

    if (t < ROWS * NACT) {
        int b = t / NACT, a = t % NACT;
        float acc = ba[a];
#pragma unroll
        for (int s = 0; s < SS; s++) {
            acc = fmaf(Wa[a * 2 * SS + s],      s2[P2_AF + s * 4 + b], acc);
            acc = fmaf(Wa[a * 2 * SS + SS + s], s2[P2_AB + s * 4 + b], acc);
        }
        s2[P2_OMG + t] = acc;
    } else if (t < ROWS * NACT + ROWS) {
        int b = t - ROWS * NACT;
        float acc = bc[0];
#pragma unroll
        for (int s = 0; s < SS; s++) {
            acc = fmaf(Wc[s],      s2[P2_AF + s * 4 + b], acc);
            acc = fmaf(Wc[SS + s], s2[P2_AB + s * 4 + b], acc);
        }
        out[(size_t)BATCH * NACT + (size_t)BATCH * NROLE * NN + row0 + b] = acc;
    }

    for (int idx = t; idx < ROWS * NROLE * NN; idx += P2NT) {
        int n = idx % NN;
        int r = (idx / NN) % NROLE;
        int b = idx / (NROLE * NN);
        size_t gg = ((size_t)(row0 + b) * NROLE + r) * NN + n;
        float v = g_psi_f[gg] + g_psi_b[gg] + bu[r];
        float m = s2[P2_HAS + b * NN + n];
        s2[P2_PSI + idx] = m * v - 60.f * (1.f - m);
    }
    __syncthreads();

    if (t < ROWS) {
        float mx = -1e30f;
        for (int a = 0; a < NACT; a++) mx = fmaxf(mx, s2[P2_OMG + t * NACT + a]);
        float e[NACT], ssum = 0.f;
        for (int a = 0; a < NACT; a++) {
            e[a] = __expf(s2[P2_OMG + t * NACT + a] - mx);
            ssum += e[a];
        }
        float inv = __fdividef(1.f, ssum);
        for (int a = 0; a < NACT; a++) out[(size_t)(row0 + t) * NACT + a] = e[a] * inv;
    }

    for (int p0 = t; p0 < ROWS * NROLE; p0 += P2NT) {
        int b = p0 / NROLE, r = p0 % NROLE;
        float* rowp = &s2[P2_PSI + (b * NROLE + r) * NN];
        float mx = -1e30f;
        for (int n = 0; n < NN; n++) mx = fmaxf(mx, rowp[n]);
        float ssum = 0.f;
        for (int n = 0; n < NN; n++) { float e = __expf(rowp[n] - mx); rowp[n] = e; ssum += e; }
        float inv = __fdividef(1.f, ssum);
        float* op = out + (size_t)BATCH * NACT + (size_t)(row0 + b) * NROLE * NN + (size_t)r * NN;
        for (int n = 0; n < NN; n++) op[n] = rowp[n] * inv;
    }
}

extern "C" void kernel_launch(void* const* d_in, const int* in_sizes, int n_in,
                              void* d_out, int out_size)
{
    cudaFuncSetAttribute(phase1_kernel, cudaFuncAttributeMaxDynamicSharedMemorySize, SMEM_BYTES);
    dim3 grid1(NBG, 2);
    phase1_kernel<<<grid1, NT, SMEM_BYTES>>>(
        (const float*)d_in[0], (const float*)d_in[1], (const float*)d_in[2], (const int*)d_in[3],
        (const float*)d_in[4], (const float*)d_in[5], (const float*)d_in[6], (const float*)d_in[7],
        (const float*)d_in[8], (const float*)d_in[9], (const float*)d_in[10], (const float*)d_in[11],
        (const float*)d_in[12], (const float*)d_in[13], (const float*)d_in[14], (const float*)d_in[15],
        (const float*)d_in[20]);
    phase2_kernel<<<NBG, P2NT>>>(
        (const float*)d_in[2],
        (const float*)d_in[16], (const float*)d_in[17], (const float*)d_in[18], (const float*)d_in[19],
        (const float*)d_in[21], (float*)d_out);
}